// round 7
// baseline (speedup 1.0000x reference)
#include <cuda_runtime.h>
#include <cuda_bf16.h>
#include <math.h>
#include <stdint.h>

#define NN 10000
#define EE 50000
#define EA 60000      // E + N self loops
#define ED 16
#define KBI 272
#define CBI 4352      // 272*16
#define CB2 8704      // 2*CBI
#define HMAX 512

// ---------------- scratch (static device globals; no runtime alloc) ----------------
__device__ float g_h1[NN * HMAX];
__device__ float g_h2[NN * HMAX];
__device__ float g_xlr[NN * 1024];          // [node][xl(dout) | xr(dout)]
__device__ float g_alpha[EA];
__device__ float g_w[EA];
__device__ float g_cnt[NN];
__device__ float g_msum[NN * ED];
__device__ float g_mean[NN * ED];
__device__ int   g_deg[NN];
__device__ int   g_off[NN + 1];
__device__ int   g_pos[NN];
__device__ int   g_eid[EA];
__device__ float g_Wlr[HMAX * 1024];        // packed [K][Wl | Wr]
__device__ float g_UV[HMAX * CB2];          // packed [i][U | V]
__device__ __nv_bfloat16 g_ABb[(size_t)NN * CB2];   // per-node factors, bf16

// ---------------- helpers ----------------
__device__ __forceinline__ uint32_t bfpair(float lo, float hi) {
    __nv_bfloat162 h2 = __floats2bfloat162_rn(lo, hi);
    return *reinterpret_cast<uint32_t*>(&h2);
}

// ---------------- edge_attr mean per dst (self-loop fill 'mean') ----------------
__global__ void k_count(const int* __restrict__ dst, const float* __restrict__ ea) {
    int idx = blockIdx.x * blockDim.x + threadIdx.x;
    if (idx >= EE * ED) return;
    int e = idx >> 4, j = idx & 15;
    int d = dst[e];
    atomicAdd(&g_msum[d * ED + j], ea[idx]);
    if (j == 0) atomicAdd(&g_cnt[d], 1.0f);
}
__global__ void k_mean() {
    int idx = blockIdx.x * blockDim.x + threadIdx.x;
    if (idx >= NN * ED) return;
    g_mean[idx] = g_msum[idx] / fmaxf(g_cnt[idx >> 4], 1.0f);
}

// ---------------- CSR build over augmented edges (dst = sort key) ----------------
__global__ void k_deg(const int* __restrict__ dst) {
    int e = blockIdx.x * blockDim.x + threadIdx.x;
    if (e >= EA) return;
    int d = (e < EE) ? dst[e] : (e - EE);
    atomicAdd(&g_deg[d], 1);
}
__global__ void k_scan() {   // single block, 256 threads
    __shared__ int sh[256];
    int tid = threadIdx.x;
    int base = 0;
    for (int start = 0; start < NN; start += 256) {
        int v = (start + tid < NN) ? g_deg[start + tid] : 0;
        sh[tid] = v;
        __syncthreads();
        for (int o = 1; o < 256; o <<= 1) {
            int t = (tid >= o) ? sh[tid - o] : 0;
            __syncthreads();
            sh[tid] += t;
            __syncthreads();
        }
        if (start + tid < NN) g_off[start + tid + 1] = base + sh[tid];
        base += sh[255];
        __syncthreads();
    }
    if (tid == 0) g_off[0] = 0;
}
__global__ void k_fill(const int* __restrict__ dst) {
    int e = blockIdx.x * blockDim.x + threadIdx.x;
    if (e >= EA) return;
    int d = (e < EE) ? dst[e] : (e - EE);
    int p = atomicAdd(&g_pos[d], 1);
    g_eid[g_off[d] + p] = e;
}

// ---------------- BF16 tensor-core GEMM: C[M,N] = A[M,K] * B[K,N], row-major fp32 in --
// BM=BN=128, BK=32, 256 threads = 8 warps (4 in M x 2 in N), warp tile 32x64.
// Output fp32 or bf16. Requires: N % 128 == 0, K % 32 == 0.
template <typename OutT>
__global__ __launch_bounds__(256) void bf16gemm(
        const float* __restrict__ A, const float* __restrict__ Bm,
        OutT* __restrict__ C, int M, int N, int K) {
    __shared__ uint32_t As[2][128][17];   // [buf][m][kpair]
    __shared__ uint32_t Bs[2][128][17];   // [buf][n][kpair]

    int tid = threadIdx.x;
    int lane = tid & 31, wid = tid >> 5;
    int g = lane >> 2, t = lane & 3;
    int wm = (wid & 3) * 32;
    int wn = (wid >> 2) * 64;
    int brow = blockIdx.y * 128;
    int bcol = blockIdx.x * 128;

    float c[2][8][4];
#pragma unroll
    for (int mi = 0; mi < 2; mi++)
#pragma unroll
        for (int nf = 0; nf < 8; nf++)
#pragma unroll
            for (int q = 0; q < 4; q++) c[mi][nf][q] = 0.0f;

    int arow = tid >> 1;
    int ahalf = tid & 1;
    bool a_ok = (brow + arow) < M;
    const float* Aip = A + (size_t)(brow + arow) * K + ahalf * 16;
    float4 a4[4];
    float4 b4[2][2];

    auto load_regs = [&](int k0) {
#pragma unroll
        for (int q = 0; q < 4; q++)
            a4[q] = a_ok ? *(const float4*)(Aip + k0 + q * 4)
                         : make_float4(0.f, 0.f, 0.f, 0.f);
#pragma unroll
        for (int s = 0; s < 2; s++) {
            int task = tid + s * 256;
            int kp = task >> 5, cg = task & 31;
            const float* bp = Bm + (size_t)(k0 + 2 * kp) * N + bcol + cg * 4;
            b4[s][0] = *(const float4*)(bp);
            b4[s][1] = *(const float4*)(bp + N);
        }
    };
    auto store_smem = [&](int buf) {
#pragma unroll
        for (int p = 0; p < 8; p++) {
            const float* f = (const float*)&a4[0];
            As[buf][arow][ahalf * 8 + p] = bfpair(f[2 * p], f[2 * p + 1]);
        }
#pragma unroll
        for (int s = 0; s < 2; s++) {
            int task = tid + s * 256;
            int kp = task >> 5, cg = task & 31;
            const float* f0 = (const float*)&b4[s][0];
            const float* f1 = (const float*)&b4[s][1];
#pragma unroll
            for (int j = 0; j < 4; j++)
                Bs[buf][cg * 4 + j][kp] = bfpair(f0[j], f1[j]);
        }
    };

    load_regs(0);
    store_smem(0);
    __syncthreads();

    int buf = 0;
    for (int k0 = 0; k0 < K; k0 += 32) {
        bool nxt = (k0 + 32) < K;
        if (nxt) load_regs(k0 + 32);
#pragma unroll
        for (int ks = 0; ks < 2; ks++) {
            uint32_t a[2][4], b[8][2];
#pragma unroll
            for (int mi = 0; mi < 2; mi++) {
                int row = wm + mi * 16 + g;
                a[mi][0] = As[buf][row][ks * 8 + t];
                a[mi][1] = As[buf][row + 8][ks * 8 + t];
                a[mi][2] = As[buf][row][ks * 8 + t + 4];
                a[mi][3] = As[buf][row + 8][ks * 8 + t + 4];
            }
#pragma unroll
            for (int nf = 0; nf < 8; nf++) {
                int col = wn + nf * 8 + g;
                b[nf][0] = Bs[buf][col][ks * 8 + t];
                b[nf][1] = Bs[buf][col][ks * 8 + t + 4];
            }
#pragma unroll
            for (int mi = 0; mi < 2; mi++)
#pragma unroll
                for (int nf = 0; nf < 8; nf++) {
                    asm volatile(
                        "mma.sync.aligned.m16n8k16.row.col.f32.bf16.bf16.f32 "
                        "{%0,%1,%2,%3}, {%4,%5,%6,%7}, {%8,%9}, {%0,%1,%2,%3};"
                        : "+f"(c[mi][nf][0]), "+f"(c[mi][nf][1]),
                          "+f"(c[mi][nf][2]), "+f"(c[mi][nf][3])
                        : "r"(a[mi][0]), "r"(a[mi][1]), "r"(a[mi][2]), "r"(a[mi][3]),
                          "r"(b[nf][0]), "r"(b[nf][1]));
                }
        }
        if (nxt) {
            store_smem(buf ^ 1);
            __syncthreads();
            buf ^= 1;
        }
    }

    // epilogue
#pragma unroll
    for (int mi = 0; mi < 2; mi++) {
        int row0 = brow + wm + mi * 16 + g;
#pragma unroll
        for (int nf = 0; nf < 8; nf++) {
            int col = bcol + wn + nf * 8 + 2 * t;
            if (sizeof(OutT) == 4) {
                float* Cf = (float*)C;
                if (row0 < M)
                    *(float2*)(Cf + (size_t)row0 * N + col) = make_float2(c[mi][nf][0], c[mi][nf][1]);
                if (row0 + 8 < M)
                    *(float2*)(Cf + (size_t)(row0 + 8) * N + col) = make_float2(c[mi][nf][2], c[mi][nf][3]);
            } else {
                __nv_bfloat16* Cb = (__nv_bfloat16*)C;
                if (row0 < M)
                    *(uint32_t*)(Cb + (size_t)row0 * N + col) = bfpair(c[mi][nf][0], c[mi][nf][1]);
                if (row0 + 8 < M)
                    *(uint32_t*)(Cb + (size_t)(row0 + 8) * N + col) = bfpair(c[mi][nf][2], c[mi][nf][3]);
            }
        }
    }
}

// ---------------- pack Wl|Wr -> g_Wlr [K][2*dout] ----------------
__global__ void k_packW(const float* __restrict__ Wl, const float* __restrict__ Wr,
                        int K, int dout) {
    int idx = blockIdx.x * blockDim.x + threadIdx.x;
    if (idx >= K * 2 * dout) return;
    int k = idx / (2 * dout), c = idx % (2 * dout);
    g_Wlr[idx] = (c < dout) ? Wl[k * dout + c] : Wr[k * dout + c - dout];
}

// ---------------- GAT per-edge attention score (one warp per augmented edge) ----------------
__global__ void k_alpha(const int* __restrict__ src, const int* __restrict__ dst,
                        const float* __restrict__ ea,
                        const float* __restrict__ We, const float* __restrict__ att,
                        int dout) {
    int e = (blockIdx.x * blockDim.x + threadIdx.x) >> 5;
    int lane = threadIdx.x & 31;
    if (e >= EA) return;
    int s, d;
    const float* eap;
    if (e < EE) { s = src[e]; d = dst[e]; eap = ea + (size_t)e * ED; }
    else        { s = d = e - EE;         eap = g_mean + (size_t)(e - EE) * ED; }
    float eav[ED];
#pragma unroll
    for (int j = 0; j < ED; j++) eav[j] = eap[j];
    const float* xlp = g_xlr + (size_t)s * 2 * dout;
    const float* xrp = g_xlr + (size_t)d * 2 * dout + dout;
    float acc = 0.0f;
    for (int dd = lane; dd < dout; dd += 32) {
        float v = xlp[dd] + xrp[dd];
        float eed = 0.0f;
#pragma unroll
        for (int j = 0; j < ED; j++) eed += eav[j] * We[j * dout + dd];
        v += eed;
        v = v > 0.0f ? v : 0.2f * v;
        acc += att[dd] * v;
    }
#pragma unroll
    for (int o = 16; o; o >>= 1) acc += __shfl_down_sync(0xffffffffu, acc, o);
    if (lane == 0) g_alpha[e] = acc;
}

// ---------------- per-node softmax over incoming edges (CSR, thread per node) ------------
__global__ void k_softmax() {
    int n = blockIdx.x * blockDim.x + threadIdx.x;
    if (n >= NN) return;
    int beg = g_off[n], end = g_off[n + 1];
    float m = -1e30f;
    for (int i = beg; i < end; i++) m = fmaxf(m, g_alpha[g_eid[i]]);
    float den = 0.0f;
    for (int i = beg; i < end; i++) {
        int e = g_eid[i];
        float ex = expf(g_alpha[e] - m);
        g_w[e] = ex;
        den += ex;
    }
    float inv = 1.0f / fmaxf(den, 1e-16f);
    for (int i = beg; i < end; i++) g_w[g_eid[i]] *= inv;
}

// ---------------- per-node aggregation (CSR, warp per node), bias + optional relu -------
__global__ void k_aggcsr(const int* __restrict__ src, const float* __restrict__ b,
                         float* __restrict__ hn, int dout, int dorelu) {
    int n = blockIdx.x * (blockDim.x >> 5) + (threadIdx.x >> 5);
    int lane = threadIdx.x & 31;
    if (n >= NN) return;
    int beg = g_off[n], end = g_off[n + 1];
    int nc = dout >> 5;            // 8 or 16
    float acc[16];
    for (int q = 0; q < nc; q++) acc[q] = b[lane + q * 32];
    for (int i = beg; i < end; i++) {
        int e = g_eid[i];
        int s = (e < EE) ? src[e] : (e - EE);
        float w = g_w[e];
        const float* xp = g_xlr + (size_t)s * 2 * dout;   // xl half
        for (int q = 0; q < nc; q++) acc[q] += w * xp[lane + q * 32];
    }
    float* hp = hn + (size_t)n * dout;
    if (dorelu)
        for (int q = 0; q < nc; q++) hp[lane + q * 32] = fmaxf(acc[q], 0.0f);
    else
        for (int q = 0; q < nc; q++) hp[lane + q * 32] = acc[q];
}

// ---------------- pack Wbi[k,i,j] -> g_UV[i][U(c) | V(c)] ----------------
__global__ void k_pack(const float* __restrict__ Wbi) {
    int idx = blockIdx.x * blockDim.x + threadIdx.x;
    if (idx >= HMAX * CB2) return;
    int i = idx / CB2, c = idx % CB2;
    int isV = (c >= CBI);
    int cc = isV ? c - CBI : c;
    int k = cc >> 4, j = cc & 15;
    g_UV[idx] = Wbi[((size_t)k * 1024 + isV * 512 + i) * 16 + j];
}

// ---------------- fused edge scorer: bi -> MLP -> sigmoid; 8 edges per block ----------------
__global__ void k_score(const int* __restrict__ src, const int* __restrict__ dst,
                        const float* __restrict__ ea,
                        const float* __restrict__ bbi,
                        const float* __restrict__ Wm1, const float* __restrict__ bm1,
                        const float* __restrict__ Wm2, const float* __restrict__ bm2,
                        const float* __restrict__ Wm3, const float* __restrict__ bm3,
                        float* __restrict__ out) {
    __shared__ float s_bi[8][KBI];
    __shared__ float s_m1[8][KBI];
    __shared__ float s_m2[8][32];
    int tid = threadIdx.x, w = tid >> 5, lane = tid & 31;
    int e0 = blockIdx.x * 8;
    int e = e0 + w;
    if (e < EE) {
        int s = src[e], d = dst[e];
        int j = lane & 15;
        float eaj = ea[(size_t)e * ED + j];
        const __nv_bfloat16* Ap = g_ABb + (size_t)s * CB2;          // U half
        const __nv_bfloat16* Bp = g_ABb + (size_t)d * CB2 + CBI;    // V half
        for (int it = 0; it < 136; it++) {
            int idx = it * 32 + lane;  // = k*16 + j
            float v = (__bfloat162float(Ap[idx]) + __bfloat162float(Bp[idx])) * eaj;
            v += __shfl_down_sync(0xffffffffu, v, 8);
            v += __shfl_down_sync(0xffffffffu, v, 4);
            v += __shfl_down_sync(0xffffffffu, v, 2);
            v += __shfl_down_sync(0xffffffffu, v, 1);
            if (j == 0) {
                int k = it * 2 + (lane >> 4);
                s_bi[w][k] = v + bbi[k];
            }
        }
    } else {
        for (int k = lane; k < KBI; k += 32) s_bi[w][k] = 0.0f;
    }
    __syncthreads();
    // m1 = relu(bi @ Wm1 + bm1)   [272]
    for (int o = tid; o < KBI; o += 256) {
        float acc[8];
        float bv = bm1[o];
#pragma unroll
        for (int q = 0; q < 8; q++) acc[q] = bv;
        for (int k = 0; k < KBI; k++) {
            float wv = Wm1[(size_t)k * KBI + o];
#pragma unroll
            for (int q = 0; q < 8; q++) acc[q] += s_bi[q][k] * wv;
        }
#pragma unroll
        for (int q = 0; q < 8; q++) s_m1[q][o] = fmaxf(acc[q], 0.0f);
    }
    __syncthreads();
    // m2 = relu(m1 @ Wm2 + bm2)   [32]
    {
        int o = tid & 31, q = tid >> 5;
        float acc = bm2[o];
        for (int k = 0; k < KBI; k++) acc += s_m1[q][k] * Wm2[(size_t)k * 32 + o];
        s_m2[q][o] = fmaxf(acc, 0.0f);
    }
    __syncthreads();
    if (e < EE) {
        float p = s_m2[w][lane] * Wm3[lane];
#pragma unroll
        for (int o = 16; o; o >>= 1) p += __shfl_down_sync(0xffffffffu, p, o);
        if (lane == 0) out[e] = 1.0f / (1.0f + expf(-(p + bm3[0])));
    }
}

// ---------------- host ----------------
static inline dim3 gemm_grid(int M, int Nn) { return dim3(Nn / 128, (M + 127) / 128); }

extern "C" void kernel_launch(void* const* d_in, const int* in_sizes, int n_in,
                              void* d_out, int out_size) {
    const float* x         = (const float*)d_in[0];
    const float* edge_attr = (const float*)d_in[1];
    const int*   eidx      = (const int*)d_in[2];
    const int* src = eidx;
    const int* dst = eidx + EE;
    const float *Wl[4], *Wr[4], *We[4], *att[4], *bb[4];
    for (int l = 0; l < 4; l++) {
        int base = 3 + l * 5;
        Wl[l]  = (const float*)d_in[base + 0];
        Wr[l]  = (const float*)d_in[base + 1];
        We[l]  = (const float*)d_in[base + 2];
        att[l] = (const float*)d_in[base + 3];
        bb[l]  = (const float*)d_in[base + 4];
    }
    const float* Wbi = (const float*)d_in[23];
    const float* bbi = (const float*)d_in[24];
    const float* Wm1 = (const float*)d_in[25];
    const float* bm1 = (const float*)d_in[26];
    const float* Wm2 = (const float*)d_in[27];
    const float* bm2 = (const float*)d_in[28];
    const float* Wm3 = (const float*)d_in[29];
    const float* bm3 = (const float*)d_in[30];
    float* out = (float*)d_out;

    // scratch pointers
    float *h1, *h2, *xlr, *Wlr, *UV, *cnt, *msum;
    __nv_bfloat16* ABb;
    int *deg, *pos;
    cudaGetSymbolAddress((void**)&h1, g_h1);
    cudaGetSymbolAddress((void**)&h2, g_h2);
    cudaGetSymbolAddress((void**)&xlr, g_xlr);
    cudaGetSymbolAddress((void**)&Wlr, g_Wlr);
    cudaGetSymbolAddress((void**)&UV, g_UV);
    cudaGetSymbolAddress((void**)&ABb, g_ABb);
    cudaGetSymbolAddress((void**)&cnt, g_cnt);
    cudaGetSymbolAddress((void**)&msum, g_msum);
    cudaGetSymbolAddress((void**)&deg, g_deg);
    cudaGetSymbolAddress((void**)&pos, g_pos);

    // edge_attr mean for self loops
    cudaMemsetAsync(cnt, 0, NN * sizeof(float));
    cudaMemsetAsync(msum, 0, NN * ED * sizeof(float));
    k_count<<<(EE * ED + 255) / 256, 256>>>(dst, edge_attr);
    k_mean<<<(NN * ED + 255) / 256, 256>>>();

    // CSR build (augmented graph, keyed by dst)
    cudaMemsetAsync(deg, 0, NN * sizeof(int));
    cudaMemsetAsync(pos, 0, NN * sizeof(int));
    k_deg<<<(EA + 255) / 256, 256>>>(dst);
    k_scan<<<1, 256>>>();
    k_fill<<<(EA + 255) / 256, 256>>>(dst);

    const float* hcur = x;
    int din = 32;
    float* hbufs[2] = { h1, h2 };
    const int warps_grid = (EA * 32 + 255) / 256;

    for (int l = 0; l < 4; l++) {
        int dout = (l == 0) ? 256 : 512;
        k_packW<<<(din * 2 * dout + 255) / 256, 256>>>(Wl[l], Wr[l], din, dout);
        bf16gemm<float><<<gemm_grid(NN, 2 * dout), 256>>>(hcur, Wlr, xlr, NN, 2 * dout, din);
        k_alpha<<<warps_grid, 256>>>(src, dst, edge_attr, We[l], att[l], dout);
        k_softmax<<<(NN + 255) / 256, 256>>>();
        float* hn = hbufs[l & 1];
        k_aggcsr<<<(NN + 7) / 8, 256>>>(src, bb[l], hn, dout, (l < 3) ? 1 : 0);
        hcur = hn;
        din = dout;
    }

    // edge scoring
    k_pack<<<(HMAX * CB2 + 255) / 256, 256>>>(Wbi);
    bf16gemm<__nv_bfloat16><<<gemm_grid(NN, CB2), 256>>>(hcur, UV, ABb, NN, CB2, HMAX);
    k_score<<<(EE + 7) / 8, 256>>>(src, dst, edge_attr, bbi, Wm1, bm1, Wm2, bm2, Wm3, bm3, out);
}

// round 8
// speedup vs baseline: 1.4672x; 1.4672x over previous
#include <cuda_runtime.h>
#include <cuda_bf16.h>
#include <math.h>
#include <stdint.h>

#define NN 10000
#define EE 50000
#define EA 60000      // E + N self loops
#define ED 16
#define KBI 272
#define CBI 4352      // 272*16
#define CB2 8704      // 2*CBI
#define HMAX 512
#define KP 288        // KBI padded (bias row at 272)
#define NP 384        // KBI padded to N%128

// ---------------- scratch (static device globals; no runtime alloc) ----------------
__device__ float g_h1[NN * HMAX];
__device__ float g_h2[NN * HMAX];
__device__ float g_xlr[NN * 1024];          // [node][xl(dout) | xr(dout)]
__device__ float g_cnt[NN];
__device__ float g_msum[NN * ED];
__device__ float g_mean[NN * ED];
__device__ int   g_deg[NN];
__device__ int   g_off[NN + 1];
__device__ int   g_pos[NN];
__device__ int   g_eid[EA];
__device__ float g_Wlr[HMAX * 1024];        // packed [K][Wl | Wr]
__device__ float g_UV[HMAX * CB2];          // packed [i][U | V]
__device__ __nv_bfloat16 g_ABb[(size_t)NN * CB2];   // per-node factors, bf16
__device__ float g_bi[(size_t)EE * KP];     // bilinear output + bias col
__device__ float g_m1[(size_t)EE * NP];     // relu(bi@Wm1+bm1)
__device__ float g_Wm1p[KP * NP];           // padded Wm1 with bias row

// ---------------- helpers ----------------
__device__ __forceinline__ uint32_t bfpair(float lo, float hi) {
    __nv_bfloat162 h2 = __floats2bfloat162_rn(lo, hi);
    return *reinterpret_cast<uint32_t*>(&h2);
}
__device__ __forceinline__ unsigned to_tf32(float f) {
    unsigned r;
    asm("cvt.rna.tf32.f32 %0, %1;" : "=r"(r) : "f"(f));
    return r;
}

// ---------------- edge_attr mean per dst (self-loop fill 'mean') ----------------
__global__ void k_count(const int* __restrict__ dst, const float* __restrict__ ea) {
    int idx = blockIdx.x * blockDim.x + threadIdx.x;
    if (idx >= EE * ED) return;
    int e = idx >> 4, j = idx & 15;
    int d = dst[e];
    atomicAdd(&g_msum[d * ED + j], ea[idx]);
    if (j == 0) atomicAdd(&g_cnt[d], 1.0f);
}
__global__ void k_mean() {
    int idx = blockIdx.x * blockDim.x + threadIdx.x;
    if (idx >= NN * ED) return;
    g_mean[idx] = g_msum[idx] / fmaxf(g_cnt[idx >> 4], 1.0f);
}

// ---------------- CSR build over augmented edges (dst = sort key) ----------------
__global__ void k_deg(const int* __restrict__ dst) {
    int e = blockIdx.x * blockDim.x + threadIdx.x;
    if (e >= EA) return;
    int d = (e < EE) ? dst[e] : (e - EE);
    atomicAdd(&g_deg[d], 1);
}
__global__ void k_scan() {   // single block, 1024 threads, warp-shuffle scan
    __shared__ int wsum[32];
    int tid = threadIdx.x, lane = tid & 31, w = tid >> 5;
    int base = 0;
    for (int start = 0; start < NN; start += 1024) {
        int i = start + tid;
        int x = (i < NN) ? g_deg[i] : 0;
#pragma unroll
        for (int o = 1; o < 32; o <<= 1) {
            int t = __shfl_up_sync(0xffffffffu, x, o);
            if (lane >= o) x += t;
        }
        if (lane == 31) wsum[w] = x;
        __syncthreads();
        if (w == 0) {
            int s = wsum[lane];
#pragma unroll
            for (int o = 1; o < 32; o <<= 1) {
                int t = __shfl_up_sync(0xffffffffu, s, o);
                if (lane >= o) s += t;
            }
            wsum[lane] = s;
        }
        __syncthreads();
        int off = (w > 0) ? wsum[w - 1] : 0;
        if (i < NN) g_off[i + 1] = base + off + x;
        base += wsum[31];
        __syncthreads();
    }
    if (tid == 0) g_off[0] = 0;
}
__global__ void k_fill(const int* __restrict__ dst) {
    int e = blockIdx.x * blockDim.x + threadIdx.x;
    if (e >= EA) return;
    int d = (e < EE) ? dst[e] : (e - EE);
    int p = atomicAdd(&g_pos[d], 1);
    g_eid[g_off[d] + p] = e;
}

// ---------------- BF16 tensor-core GEMM: C[M,N] = A[M,K] * B[K,N], row-major fp32 in --
template <typename OutT>
__global__ __launch_bounds__(256) void bf16gemm(
        const float* __restrict__ A, const float* __restrict__ Bm,
        OutT* __restrict__ C, int M, int N, int K) {
    __shared__ uint32_t As[2][128][17];
    __shared__ uint32_t Bs[2][128][17];

    int tid = threadIdx.x;
    int lane = tid & 31, wid = tid >> 5;
    int g = lane >> 2, t = lane & 3;
    int wm = (wid & 3) * 32;
    int wn = (wid >> 2) * 64;
    int brow = blockIdx.y * 128;
    int bcol = blockIdx.x * 128;

    float c[2][8][4];
#pragma unroll
    for (int mi = 0; mi < 2; mi++)
#pragma unroll
        for (int nf = 0; nf < 8; nf++)
#pragma unroll
            for (int q = 0; q < 4; q++) c[mi][nf][q] = 0.0f;

    int arow = tid >> 1;
    int ahalf = tid & 1;
    bool a_ok = (brow + arow) < M;
    const float* Aip = A + (size_t)(brow + arow) * K + ahalf * 16;
    float4 a4[4];
    float4 b4[2][2];

    auto load_regs = [&](int k0) {
#pragma unroll
        for (int q = 0; q < 4; q++)
            a4[q] = a_ok ? *(const float4*)(Aip + k0 + q * 4)
                         : make_float4(0.f, 0.f, 0.f, 0.f);
#pragma unroll
        for (int s = 0; s < 2; s++) {
            int task = tid + s * 256;
            int kp = task >> 5, cg = task & 31;
            const float* bp = Bm + (size_t)(k0 + 2 * kp) * N + bcol + cg * 4;
            b4[s][0] = *(const float4*)(bp);
            b4[s][1] = *(const float4*)(bp + N);
        }
    };
    auto store_smem = [&](int buf) {
#pragma unroll
        for (int p = 0; p < 8; p++) {
            const float* f = (const float*)&a4[0];
            As[buf][arow][ahalf * 8 + p] = bfpair(f[2 * p], f[2 * p + 1]);
        }
#pragma unroll
        for (int s = 0; s < 2; s++) {
            int task = tid + s * 256;
            int kp = task >> 5, cg = task & 31;
            const float* f0 = (const float*)&b4[s][0];
            const float* f1 = (const float*)&b4[s][1];
#pragma unroll
            for (int j = 0; j < 4; j++)
                Bs[buf][cg * 4 + j][kp] = bfpair(f0[j], f1[j]);
        }
    };

    load_regs(0);
    store_smem(0);
    __syncthreads();

    int buf = 0;
    for (int k0 = 0; k0 < K; k0 += 32) {
        bool nxt = (k0 + 32) < K;
        if (nxt) load_regs(k0 + 32);
#pragma unroll
        for (int ks = 0; ks < 2; ks++) {
            uint32_t a[2][4], b[8][2];
#pragma unroll
            for (int mi = 0; mi < 2; mi++) {
                int row = wm + mi * 16 + g;
                a[mi][0] = As[buf][row][ks * 8 + t];
                a[mi][1] = As[buf][row + 8][ks * 8 + t];
                a[mi][2] = As[buf][row][ks * 8 + t + 4];
                a[mi][3] = As[buf][row + 8][ks * 8 + t + 4];
            }
#pragma unroll
            for (int nf = 0; nf < 8; nf++) {
                int col = wn + nf * 8 + g;
                b[nf][0] = Bs[buf][col][ks * 8 + t];
                b[nf][1] = Bs[buf][col][ks * 8 + t + 4];
            }
#pragma unroll
            for (int mi = 0; mi < 2; mi++)
#pragma unroll
                for (int nf = 0; nf < 8; nf++) {
                    asm volatile(
                        "mma.sync.aligned.m16n8k16.row.col.f32.bf16.bf16.f32 "
                        "{%0,%1,%2,%3}, {%4,%5,%6,%7}, {%8,%9}, {%0,%1,%2,%3};"
                        : "+f"(c[mi][nf][0]), "+f"(c[mi][nf][1]),
                          "+f"(c[mi][nf][2]), "+f"(c[mi][nf][3])
                        : "r"(a[mi][0]), "r"(a[mi][1]), "r"(a[mi][2]), "r"(a[mi][3]),
                          "r"(b[nf][0]), "r"(b[nf][1]));
                }
        }
        if (nxt) {
            store_smem(buf ^ 1);
            __syncthreads();
            buf ^= 1;
        }
    }

#pragma unroll
    for (int mi = 0; mi < 2; mi++) {
        int row0 = brow + wm + mi * 16 + g;
#pragma unroll
        for (int nf = 0; nf < 8; nf++) {
            int col = bcol + wn + nf * 8 + 2 * t;
            if (sizeof(OutT) == 4) {
                float* Cf = (float*)C;
                if (row0 < M)
                    *(float2*)(Cf + (size_t)row0 * N + col) = make_float2(c[mi][nf][0], c[mi][nf][1]);
                if (row0 + 8 < M)
                    *(float2*)(Cf + (size_t)(row0 + 8) * N + col) = make_float2(c[mi][nf][2], c[mi][nf][3]);
            } else {
                __nv_bfloat16* Cb = (__nv_bfloat16*)C;
                if (row0 < M)
                    *(uint32_t*)(Cb + (size_t)row0 * N + col) = bfpair(c[mi][nf][0], c[mi][nf][1]);
                if (row0 + 8 < M)
                    *(uint32_t*)(Cb + (size_t)(row0 + 8) * N + col) = bfpair(c[mi][nf][2], c[mi][nf][3]);
            }
        }
    }
}

// ---------------- TF32 tensor-core GEMM (for m1; higher precision), optional ReLU --------
// BM=BN=128, BK=16, 256 threads. N % 128 == 0, K % 16 == 0, M guarded.
template <bool RELU>
__global__ __launch_bounds__(256) void tf32gemm(
        const float* __restrict__ A, const float* __restrict__ Bm,
        float* __restrict__ C, int M, int N, int K) {
    __shared__ unsigned As[16][132];
    __shared__ unsigned Bs[16][132];

    int tid = threadIdx.x;
    int lane = tid & 31, wid = tid >> 5;
    int g = lane >> 2, t = lane & 3;
    int wm = (wid & 3) * 32;
    int wn = (wid >> 2) * 64;
    int brow = blockIdx.y * 128;
    int bcol = blockIdx.x * 128;

    float c[2][8][4];
#pragma unroll
    for (int mi = 0; mi < 2; mi++)
#pragma unroll
        for (int nf = 0; nf < 8; nf++)
#pragma unroll
            for (int q = 0; q < 4; q++) c[mi][nf][q] = 0.0f;

    int arow = tid >> 2;
    int akc  = (tid & 3) * 4;
    int bkr  = tid >> 4;
    int bcc  = (tid & 15) * 8;

    for (int k0 = 0; k0 < K; k0 += 16) {
#pragma unroll
        for (int h = 0; h < 2; h++) {
            int r = arow + h * 64;
            float4 v = make_float4(0.f, 0.f, 0.f, 0.f);
            if (brow + r < M)
                v = *(const float4*)(A + (size_t)(brow + r) * K + k0 + akc);
            As[akc + 0][r] = to_tf32(v.x);
            As[akc + 1][r] = to_tf32(v.y);
            As[akc + 2][r] = to_tf32(v.z);
            As[akc + 3][r] = to_tf32(v.w);
        }
#pragma unroll
        for (int h = 0; h < 2; h++) {
            float4 v = *(const float4*)(Bm + (size_t)(k0 + bkr) * N + bcol + bcc + h * 4);
            Bs[bkr][bcc + h * 4 + 0] = to_tf32(v.x);
            Bs[bkr][bcc + h * 4 + 1] = to_tf32(v.y);
            Bs[bkr][bcc + h * 4 + 2] = to_tf32(v.z);
            Bs[bkr][bcc + h * 4 + 3] = to_tf32(v.w);
        }
        __syncthreads();
#pragma unroll
        for (int kk = 0; kk < 16; kk += 8) {
            unsigned a[2][4], b[8][2];
#pragma unroll
            for (int mi = 0; mi < 2; mi++) {
                int row = wm + mi * 16 + g;
                a[mi][0] = As[kk + t][row];
                a[mi][1] = As[kk + t][row + 8];
                a[mi][2] = As[kk + t + 4][row];
                a[mi][3] = As[kk + t + 4][row + 8];
            }
#pragma unroll
            for (int nf = 0; nf < 8; nf++) {
                int col = wn + nf * 8 + g;
                b[nf][0] = Bs[kk + t][col];
                b[nf][1] = Bs[kk + t + 4][col];
            }
#pragma unroll
            for (int mi = 0; mi < 2; mi++)
#pragma unroll
                for (int nf = 0; nf < 8; nf++) {
                    asm volatile(
                        "mma.sync.aligned.m16n8k8.row.col.f32.tf32.tf32.f32 "
                        "{%0,%1,%2,%3}, {%4,%5,%6,%7}, {%8,%9}, {%0,%1,%2,%3};"
                        : "+f"(c[mi][nf][0]), "+f"(c[mi][nf][1]),
                          "+f"(c[mi][nf][2]), "+f"(c[mi][nf][3])
                        : "r"(a[mi][0]), "r"(a[mi][1]), "r"(a[mi][2]), "r"(a[mi][3]),
                          "r"(b[nf][0]), "r"(b[nf][1]));
                }
        }
        __syncthreads();
    }

#pragma unroll
    for (int mi = 0; mi < 2; mi++) {
        int row0 = brow + wm + mi * 16 + g;
#pragma unroll
        for (int nf = 0; nf < 8; nf++) {
            int col = bcol + wn + nf * 8 + 2 * t;
            float v0 = c[mi][nf][0], v1 = c[mi][nf][1];
            float v2 = c[mi][nf][2], v3 = c[mi][nf][3];
            if (RELU) {
                v0 = fmaxf(v0, 0.f); v1 = fmaxf(v1, 0.f);
                v2 = fmaxf(v2, 0.f); v3 = fmaxf(v3, 0.f);
            }
            if (row0 < M)
                *(float2*)(C + (size_t)row0 * N + col) = make_float2(v0, v1);
            if (row0 + 8 < M)
                *(float2*)(C + (size_t)(row0 + 8) * N + col) = make_float2(v2, v3);
        }
    }
}

// ---------------- pack Wl|Wr -> g_Wlr [K][2*dout] ----------------
__global__ void k_packW(const float* __restrict__ Wl, const float* __restrict__ Wr,
                        int K, int dout) {
    int idx = blockIdx.x * blockDim.x + threadIdx.x;
    if (idx >= K * 2 * dout) return;
    int k = idx / (2 * dout), c = idx % (2 * dout);
    g_Wlr[idx] = (c < dout) ? Wl[k * dout + c] : Wr[k * dout + c - dout];
}

// ---------------- fused GAT layer: alpha + online softmax + aggregation (warp/node) ------
template <int NC>   // NC = dout/32
__global__ __launch_bounds__(256) void k_gat(
        const int* __restrict__ src, const float* __restrict__ ea,
        const float* __restrict__ We, const float* __restrict__ att,
        const float* __restrict__ bias, float* __restrict__ hn, int dorelu) {
    const int dout = NC * 32;
    __shared__ float sWe[ED][NC * 32];
    __shared__ float sAtt[NC * 32];
    __shared__ float sB[NC * 32];
    int tid = threadIdx.x;
    for (int i = tid; i < ED * dout; i += 256) sWe[i / dout][i % dout] = We[i];
    for (int i = tid; i < dout; i += 256) { sAtt[i] = att[i]; sB[i] = bias[i]; }
    __syncthreads();

    int lane = tid & 31, w = tid >> 5;
    int n = blockIdx.x * 8 + w;
    if (n >= NN) return;

    const float* xrp = g_xlr + (size_t)n * 2 * dout + dout;
    float xrv[NC];
#pragma unroll
    for (int q = 0; q < NC; q++) xrv[q] = xrp[q * 32 + lane];

    float m = -1e30f, ssum = 0.0f;
    float acc[NC];
#pragma unroll
    for (int q = 0; q < NC; q++) acc[q] = 0.0f;

    int beg = g_off[n], end = g_off[n + 1];
    for (int i = beg; i < end; i++) {
        int e = g_eid[i];
        int s;
        const float* eap;
        if (e < EE) { s = src[e]; eap = ea + (size_t)e * ED; }
        else        { s = e - EE; eap = g_mean + (size_t)s * ED; }
        float eareg = (lane < ED) ? eap[lane] : 0.0f;
        const float* xlp = g_xlr + (size_t)s * 2 * dout;
        float xv[NC];
#pragma unroll
        for (int q = 0; q < NC; q++) xv[q] = xlp[q * 32 + lane];
        float ed[NC];
#pragma unroll
        for (int q = 0; q < NC; q++) ed[q] = 0.0f;
#pragma unroll
        for (int j = 0; j < ED; j++) {
            float aj = __shfl_sync(0xffffffffu, eareg, j);
#pragma unroll
            for (int q = 0; q < NC; q++) ed[q] += aj * sWe[j][q * 32 + lane];
        }
        float p = 0.0f;
#pragma unroll
        for (int q = 0; q < NC; q++) {
            float v = xv[q] + xrv[q] + ed[q];
            v = v > 0.0f ? v : 0.2f * v;
            p += sAtt[q * 32 + lane] * v;
        }
#pragma unroll
        for (int o = 16; o; o >>= 1) p += __shfl_xor_sync(0xffffffffu, p, o);
        // online softmax update
        float nm = fmaxf(m, p);
        float cs = expf(m - nm);
        float ex = expf(p - nm);
        ssum = ssum * cs + ex;
#pragma unroll
        for (int q = 0; q < NC; q++) acc[q] = acc[q] * cs + ex * xv[q];
        m = nm;
    }
    float inv = 1.0f / fmaxf(ssum, 1e-16f);
    float* hp = hn + (size_t)n * dout;
#pragma unroll
    for (int q = 0; q < NC; q++) {
        float v = acc[q] * inv + sB[q * 32 + lane];
        hp[q * 32 + lane] = dorelu ? fmaxf(v, 0.0f) : v;
    }
}

// ---------------- pack Wbi[k,i,j] -> g_UV[i][U(c) | V(c)] ----------------
__global__ void k_pack(const float* __restrict__ Wbi) {
    int idx = blockIdx.x * blockDim.x + threadIdx.x;
    if (idx >= HMAX * CB2) return;
    int i = idx / CB2, c = idx % CB2;
    int isV = (c >= CBI);
    int cc = isV ? c - CBI : c;
    int k = cc >> 4, j = cc & 15;
    g_UV[idx] = Wbi[((size_t)k * 1024 + isV * 512 + i) * 16 + j];
}

// ---------------- pad Wm1 into [KP][NP] with bias row ----------------
__global__ void k_packM1(const float* __restrict__ Wm1, const float* __restrict__ bm1) {
    int idx = blockIdx.x * blockDim.x + threadIdx.x;
    if (idx >= KP * NP) return;
    int r = idx / NP, c = idx % NP;
    float v = 0.0f;
    if (c < KBI) {
        if (r < KBI) v = Wm1[(size_t)r * KBI + c];
        else if (r == KBI) v = bm1[c];
    }
    g_Wm1p[idx] = v;
}

// ---------------- bilinear: bi[e][k] = sum_j (A[src]+B[dst])[k*16+j]*ea[j] + bbi[k] -------
__global__ void k_bilin(const int* __restrict__ src, const int* __restrict__ dst,
                        const float* __restrict__ ea, const float* __restrict__ bbi) {
    int tid = threadIdx.x, w = tid >> 5, lane = tid & 31;
    int e = blockIdx.x * 8 + w;
    if (e >= EE) return;
    int s = src[e], d = dst[e];
    int j4 = lane & 3, kk = lane >> 2;
    float4 eav = *(const float4*)(ea + (size_t)e * ED + j4 * 4);
    const __nv_bfloat16* Ap = g_ABb + (size_t)s * CB2;
    const __nv_bfloat16* Bp = g_ABb + (size_t)d * CB2 + CBI;
    float* bo = g_bi + (size_t)e * KP;
#pragma unroll 4
    for (int it = 0; it < 34; it++) {
        int base = (it * 8 + kk) * 16 + j4 * 4;
        float2 a01 = __bfloat1622float2(*(const __nv_bfloat162*)(Ap + base));
        float2 a23 = __bfloat1622float2(*(const __nv_bfloat162*)(Ap + base + 2));
        float2 b01 = __bfloat1622float2(*(const __nv_bfloat162*)(Bp + base));
        float2 b23 = __bfloat1622float2(*(const __nv_bfloat162*)(Bp + base + 2));
        float v = (a01.x + b01.x) * eav.x + (a01.y + b01.y) * eav.y
                + (a23.x + b23.x) * eav.z + (a23.y + b23.y) * eav.w;
        v += __shfl_xor_sync(0xffffffffu, v, 1);
        v += __shfl_xor_sync(0xffffffffu, v, 2);
        if (j4 == 0) {
            int k = it * 8 + kk;
            bo[k] = v + bbi[k];
        }
    }
    if (lane < KP - KBI) bo[KBI + lane] = (lane == 0) ? 1.0f : 0.0f;
}

// ---------------- tail: m2 = relu(m1@Wm2+bm2); out = sigmoid(m2@Wm3+bm3) ------------------
__global__ void k_tail(const float* __restrict__ Wm2, const float* __restrict__ bm2,
                       const float* __restrict__ Wm3, const float* __restrict__ bm3,
                       float* __restrict__ out) {
    int tid = threadIdx.x, w = tid >> 5, lane = tid & 31;
    int e = blockIdx.x * 8 + w;
    if (e >= EE) return;
    const float* m1p = g_m1 + (size_t)e * NP;
    float acc = bm2[lane];
    for (int k0 = 0; k0 < KBI; k0 += 32) {
        float mv = m1p[k0 + lane];           // cols >= 272 are zero (padded GEMM)
        int jmax = (KBI - k0 < 32) ? (KBI - k0) : 32;
        for (int j = 0; j < jmax; j++) {
            float m = __shfl_sync(0xffffffffu, mv, j);
            acc += m * Wm2[(size_t)(k0 + j) * 32 + lane];
        }
    }
    float m2v = fmaxf(acc, 0.0f);
    float p = m2v * Wm3[lane];
#pragma unroll
    for (int o = 16; o; o >>= 1) p += __shfl_xor_sync(0xffffffffu, p, o);
    if (lane == 0) out[e] = 1.0f / (1.0f + expf(-(p + bm3[0])));
}

// ---------------- host ----------------
static inline dim3 gemm_grid(int M, int Nn) { return dim3(Nn / 128, (M + 127) / 128); }

extern "C" void kernel_launch(void* const* d_in, const int* in_sizes, int n_in,
                              void* d_out, int out_size) {
    const float* x         = (const float*)d_in[0];
    const float* edge_attr = (const float*)d_in[1];
    const int*   eidx      = (const int*)d_in[2];
    const int* src = eidx;
    const int* dst = eidx + EE;
    const float *Wl[4], *Wr[4], *We[4], *att[4], *bb[4];
    for (int l = 0; l < 4; l++) {
        int base = 3 + l * 5;
        Wl[l]  = (const float*)d_in[base + 0];
        Wr[l]  = (const float*)d_in[base + 1];
        We[l]  = (const float*)d_in[base + 2];
        att[l] = (const float*)d_in[base + 3];
        bb[l]  = (const float*)d_in[base + 4];
    }
    const float* Wbi = (const float*)d_in[23];
    const float* bbi = (const float*)d_in[24];
    const float* Wm1 = (const float*)d_in[25];
    const float* bm1 = (const float*)d_in[26];
    const float* Wm2 = (const float*)d_in[27];
    const float* bm2 = (const float*)d_in[28];
    const float* Wm3 = (const float*)d_in[29];
    const float* bm3 = (const float*)d_in[30];
    float* out = (float*)d_out;

    // scratch pointers
    float *h1, *h2, *xlr, *Wlr, *UV, *cnt, *msum, *bi, *m1, *Wm1p;
    __nv_bfloat16* ABb;
    int *deg, *pos;
    cudaGetSymbolAddress((void**)&h1, g_h1);
    cudaGetSymbolAddress((void**)&h2, g_h2);
    cudaGetSymbolAddress((void**)&xlr, g_xlr);
    cudaGetSymbolAddress((void**)&Wlr, g_Wlr);
    cudaGetSymbolAddress((void**)&UV, g_UV);
    cudaGetSymbolAddress((void**)&ABb, g_ABb);
    cudaGetSymbolAddress((void**)&cnt, g_cnt);
    cudaGetSymbolAddress((void**)&msum, g_msum);
    cudaGetSymbolAddress((void**)&deg, g_deg);
    cudaGetSymbolAddress((void**)&pos, g_pos);
    cudaGetSymbolAddress((void**)&bi, g_bi);
    cudaGetSymbolAddress((void**)&m1, g_m1);
    cudaGetSymbolAddress((void**)&Wm1p, g_Wm1p);

    // edge_attr mean for self loops
    cudaMemsetAsync(cnt, 0, NN * sizeof(float));
    cudaMemsetAsync(msum, 0, NN * ED * sizeof(float));
    k_count<<<(EE * ED + 255) / 256, 256>>>(dst, edge_attr);
    k_mean<<<(NN * ED + 255) / 256, 256>>>();

    // CSR build (augmented graph, keyed by dst)
    cudaMemsetAsync(deg, 0, NN * sizeof(int));
    cudaMemsetAsync(pos, 0, NN * sizeof(int));
    k_deg<<<(EA + 255) / 256, 256>>>(dst);
    k_scan<<<1, 1024>>>();
    k_fill<<<(EA + 255) / 256, 256>>>(dst);

    const float* hcur = x;
    int din = 32;
    float* hbufs[2] = { h1, h2 };

    for (int l = 0; l < 4; l++) {
        int dout = (l == 0) ? 256 : 512;
        k_packW<<<(din * 2 * dout + 255) / 256, 256>>>(Wl[l], Wr[l], din, dout);
        bf16gemm<float><<<gemm_grid(NN, 2 * dout), 256>>>(hcur, Wlr, xlr, NN, 2 * dout, din);
        float* hn = hbufs[l & 1];
        int dorelu = (l < 3) ? 1 : 0;
        if (dout == 256)
            k_gat<8><<<(NN + 7) / 8, 256>>>(src, edge_attr, We[l], att[l], bb[l], hn, dorelu);
        else
            k_gat<16><<<(NN + 7) / 8, 256>>>(src, edge_attr, We[l], att[l], bb[l], hn, dorelu);
        hcur = hn;
        din = dout;
    }

    // edge scoring
    k_pack<<<(HMAX * CB2 + 255) / 256, 256>>>(Wbi);
    bf16gemm<__nv_bfloat16><<<gemm_grid(NN, CB2), 256>>>(hcur, UV, ABb, NN, CB2, HMAX);
    k_packM1<<<(KP * NP + 255) / 256, 256>>>(Wm1, bm1);
    k_bilin<<<(EE + 7) / 8, 256>>>(src, dst, edge_attr, bbi);
    tf32gemm<true><<<gemm_grid(EE, NP), 256>>>(bi, Wm1p, m1, EE, NP, KP);
    k_tail<<<(EE + 7) / 8, 256>>>(Wm2, bm2, Wm3, bm3, out);
}

// round 9
// speedup vs baseline: 1.6461x; 1.1219x over previous
#include <cuda_runtime.h>
#include <cuda_bf16.h>
#include <math.h>
#include <stdint.h>

#define NN 10000
#define EE 50000
#define EA 60000      // E + N self loops
#define ED 16
#define KBI 272
#define CBI 4352      // 272*16
#define CB2 8704      // 2*CBI
#define HMAX 512
#define KP 288        // KBI padded (bias row at 272)
#define NP 384        // KBI padded to N%128

// ---------------- scratch (static device globals; no runtime alloc) ----------------
__device__ float g_h1[NN * HMAX];
__device__ float g_h2[NN * HMAX];
__device__ float g_xlr[NN * 1024];          // [node][xl(dout) | xr(dout)]
__device__ float g_cnt[NN];
__device__ float g_msum[NN * ED];
__device__ float g_mean[NN * ED];
__device__ int   g_deg[NN];
__device__ int   g_off[NN + 1];
__device__ int   g_pos[NN];
__device__ int   g_eid[EA];
__device__ float g_Wlr[HMAX * 1024];        // packed [K][Wl | Wr]
__device__ float g_UV[HMAX * CB2];          // packed [i][U | V]
__device__ __nv_bfloat16 g_ABb[(size_t)NN * CB2];   // per-node factors, bf16
__device__ float g_bi[(size_t)EE * KP];     // bilinear output + bias col
__device__ float g_m1[(size_t)EE * NP];     // relu(bi@Wm1+bm1)
__device__ float g_Wm1p[KP * NP];           // padded Wm1 with bias row

// ---------------- helpers ----------------
__device__ __forceinline__ uint32_t bfpair(float lo, float hi) {
    __nv_bfloat162 h2 = __floats2bfloat162_rn(lo, hi);
    return *reinterpret_cast<uint32_t*>(&h2);
}
__device__ __forceinline__ unsigned to_tf32(float f) {
    unsigned r;
    asm("cvt.rna.tf32.f32 %0, %1;" : "=r"(r) : "f"(f));
    return r;
}
__device__ __forceinline__ void ldsm_x4(uint32_t& r0, uint32_t& r1, uint32_t& r2,
                                        uint32_t& r3, uint32_t addr) {
    asm volatile("ldmatrix.sync.aligned.m8n8.x4.shared.b16 {%0,%1,%2,%3}, [%4];"
                 : "=r"(r0), "=r"(r1), "=r"(r2), "=r"(r3) : "r"(addr));
}

// ---------------- edge_attr mean per dst (self-loop fill 'mean') ----------------
__global__ void k_count(const int* __restrict__ dst, const float* __restrict__ ea) {
    int idx = blockIdx.x * blockDim.x + threadIdx.x;
    if (idx >= EE * ED) return;
    int e = idx >> 4, j = idx & 15;
    int d = dst[e];
    atomicAdd(&g_msum[d * ED + j], ea[idx]);
    if (j == 0) atomicAdd(&g_cnt[d], 1.0f);
}
__global__ void k_mean() {
    int idx = blockIdx.x * blockDim.x + threadIdx.x;
    if (idx >= NN * ED) return;
    g_mean[idx] = g_msum[idx] / fmaxf(g_cnt[idx >> 4], 1.0f);
}

// ---------------- CSR build over augmented edges (dst = sort key) ----------------
__global__ void k_deg(const int* __restrict__ dst) {
    int e = blockIdx.x * blockDim.x + threadIdx.x;
    if (e >= EA) return;
    int d = (e < EE) ? dst[e] : (e - EE);
    atomicAdd(&g_deg[d], 1);
}
__global__ void k_scan() {   // single block, 1024 threads, warp-shuffle scan
    __shared__ int wsum[32];
    int tid = threadIdx.x, lane = tid & 31, w = tid >> 5;
    int base = 0;
    for (int start = 0; start < NN; start += 1024) {
        int i = start + tid;
        int x = (i < NN) ? g_deg[i] : 0;
#pragma unroll
        for (int o = 1; o < 32; o <<= 1) {
            int t = __shfl_up_sync(0xffffffffu, x, o);
            if (lane >= o) x += t;
        }
        if (lane == 31) wsum[w] = x;
        __syncthreads();
        if (w == 0) {
            int s = wsum[lane];
#pragma unroll
            for (int o = 1; o < 32; o <<= 1) {
                int t = __shfl_up_sync(0xffffffffu, s, o);
                if (lane >= o) s += t;
            }
            wsum[lane] = s;
        }
        __syncthreads();
        int off = (w > 0) ? wsum[w - 1] : 0;
        if (i < NN) g_off[i + 1] = base + off + x;
        base += wsum[31];
        __syncthreads();
    }
    if (tid == 0) g_off[0] = 0;
}
__global__ void k_fill(const int* __restrict__ dst) {
    int e = blockIdx.x * blockDim.x + threadIdx.x;
    if (e >= EA) return;
    int d = (e < EE) ? dst[e] : (e - EE);
    int p = atomicAdd(&g_pos[d], 1);
    g_eid[g_off[d] + p] = e;
}

// ---------------- BF16 tensor-core GEMM with ldmatrix: C[M,N]=A[M,K]*B[K,N] fp32 in ------
// BM=BN=128, BK=32, 256 threads = 8 warps (4 in M x 2 in N), warp tile 32x64.
// Smem rows: 20 uint32 stride (80B, 16B-aligned for LDSM, conflict-free reads).
// B smem uses seg-XOR ((col>>3)&3) to cut staging-store conflicts.
#define SROW 20
template <typename OutT>
__global__ __launch_bounds__(256) void bf16gemm(
        const float* __restrict__ A, const float* __restrict__ Bm,
        OutT* __restrict__ C, int M, int N, int K) {
    __shared__ uint32_t As[2][128 * SROW];
    __shared__ uint32_t Bs[2][128 * SROW];

    int tid = threadIdx.x;
    int lane = tid & 31, wid = tid >> 5;
    int g = lane >> 2, t = lane & 3;
    int wm = (wid & 3) * 32;
    int wn = (wid >> 2) * 64;
    int brow = blockIdx.y * 128;
    int bcol = blockIdx.x * 128;

    uint32_t smA = (uint32_t)__cvta_generic_to_shared(&As[0][0]);
    uint32_t smB = (uint32_t)__cvta_generic_to_shared(&Bs[0][0]);
    const uint32_t BUFB = 128 * SROW * 4;

    float c[2][8][4];
#pragma unroll
    for (int mi = 0; mi < 2; mi++)
#pragma unroll
        for (int nf = 0; nf < 8; nf++)
#pragma unroll
            for (int q = 0; q < 4; q++) c[mi][nf][q] = 0.0f;

    // A staging: thread covers row tid>>1, kpairs (tid&1)*8 .. +7
    int arow = tid >> 1;
    int ahalf = tid & 1;
    bool a_ok = (brow + arow) < M;
    const float* Aip = A + (size_t)(brow + arow) * K + ahalf * 16;
    float4 a4[4];
    float4 b4[2][2];

    auto load_regs = [&](int k0) {
#pragma unroll
        for (int q = 0; q < 4; q++)
            a4[q] = a_ok ? *(const float4*)(Aip + k0 + q * 4)
                         : make_float4(0.f, 0.f, 0.f, 0.f);
#pragma unroll
        for (int s = 0; s < 2; s++) {
            int task = tid + s * 256;
            int kp = task >> 5, cg = task & 31;
            const float* bp = Bm + (size_t)(k0 + 2 * kp) * N + bcol + cg * 4;
            b4[s][0] = *(const float4*)(bp);
            b4[s][1] = *(const float4*)(bp + N);
        }
    };
    auto store_smem = [&](int buf) {
        {
            const float* f = (const float*)&a4[0];
            uint32_t pr[8];
#pragma unroll
            for (int p = 0; p < 8; p++) pr[p] = bfpair(f[2 * p], f[2 * p + 1]);
            uint32_t* dst0 = &As[buf][arow * SROW + ahalf * 8];
            *(uint4*)dst0 = make_uint4(pr[0], pr[1], pr[2], pr[3]);
            *(uint4*)(dst0 + 4) = make_uint4(pr[4], pr[5], pr[6], pr[7]);
        }
#pragma unroll
        for (int s = 0; s < 2; s++) {
            int task = tid + s * 256;
            int kp = task >> 5, cg = task & 31;
            int seg = kp >> 2, kin = kp & 3;
            const float* f0 = (const float*)&b4[s][0];
            const float* f1 = (const float*)&b4[s][1];
#pragma unroll
            for (int j = 0; j < 4; j++) {
                int col = cg * 4 + j;
                int ps = seg ^ ((col >> 3) & 3);
                Bs[buf][col * SROW + ps * 4 + kin] = bfpair(f0[j], f1[j]);
            }
        }
    };

    load_regs(0);
    store_smem(0);
    __syncthreads();

    int buf = 0;
    for (int k0 = 0; k0 < K; k0 += 32) {
        bool nxt = (k0 + 32) < K;
        if (nxt) load_regs(k0 + 32);
        uint32_t baseA = smA + buf * BUFB;
        uint32_t baseB = smB + buf * BUFB;
#pragma unroll
        for (int ks = 0; ks < 2; ks++) {
            uint32_t a[2][4], b[8][2];
#pragma unroll
            for (int mi = 0; mi < 2; mi++) {
                int row = wm + mi * 16 + (lane & 7) + ((lane >> 3) & 1) * 8;
                int seg = ks * 2 + (lane >> 4);
                ldsm_x4(a[mi][0], a[mi][1], a[mi][2], a[mi][3],
                        baseA + (uint32_t)(row * SROW + seg * 4) * 4u);
            }
#pragma unroll
            for (int p = 0; p < 4; p++) {
                int nf = p * 2;
                int col = wn + (nf + (lane >> 4)) * 8 + (lane & 7);
                int segl = ks * 2 + ((lane >> 3) & 1);
                int seg = segl ^ ((col >> 3) & 3);
                ldsm_x4(b[nf][0], b[nf][1], b[nf + 1][0], b[nf + 1][1],
                        baseB + (uint32_t)(col * SROW + seg * 4) * 4u);
            }
#pragma unroll
            for (int mi = 0; mi < 2; mi++)
#pragma unroll
                for (int nf = 0; nf < 8; nf++) {
                    asm volatile(
                        "mma.sync.aligned.m16n8k16.row.col.f32.bf16.bf16.f32 "
                        "{%0,%1,%2,%3}, {%4,%5,%6,%7}, {%8,%9}, {%0,%1,%2,%3};"
                        : "+f"(c[mi][nf][0]), "+f"(c[mi][nf][1]),
                          "+f"(c[mi][nf][2]), "+f"(c[mi][nf][3])
                        : "r"(a[mi][0]), "r"(a[mi][1]), "r"(a[mi][2]), "r"(a[mi][3]),
                          "r"(b[nf][0]), "r"(b[nf][1]));
                }
        }
        if (nxt) {
            store_smem(buf ^ 1);
            __syncthreads();
            buf ^= 1;
        }
    }

#pragma unroll
    for (int mi = 0; mi < 2; mi++) {
        int row0 = brow + wm + mi * 16 + g;
#pragma unroll
        for (int nf = 0; nf < 8; nf++) {
            int col = bcol + wn + nf * 8 + 2 * t;
            if (sizeof(OutT) == 4) {
                float* Cf = (float*)C;
                if (row0 < M)
                    *(float2*)(Cf + (size_t)row0 * N + col) = make_float2(c[mi][nf][0], c[mi][nf][1]);
                if (row0 + 8 < M)
                    *(float2*)(Cf + (size_t)(row0 + 8) * N + col) = make_float2(c[mi][nf][2], c[mi][nf][3]);
            } else {
                __nv_bfloat16* Cb = (__nv_bfloat16*)C;
                if (row0 < M)
                    *(uint32_t*)(Cb + (size_t)row0 * N + col) = bfpair(c[mi][nf][0], c[mi][nf][1]);
                if (row0 + 8 < M)
                    *(uint32_t*)(Cb + (size_t)(row0 + 8) * N + col) = bfpair(c[mi][nf][2], c[mi][nf][3]);
            }
        }
    }
}

// ---------------- TF32 tensor-core GEMM (for m1; higher precision), optional ReLU --------
template <bool RELU>
__global__ __launch_bounds__(256) void tf32gemm(
        const float* __restrict__ A, const float* __restrict__ Bm,
        float* __restrict__ C, int M, int N, int K) {
    __shared__ unsigned As[16][132];
    __shared__ unsigned Bs[16][132];

    int tid = threadIdx.x;
    int lane = tid & 31, wid = tid >> 5;
    int g = lane >> 2, t = lane & 3;
    int wm = (wid & 3) * 32;
    int wn = (wid >> 2) * 64;
    int brow = blockIdx.y * 128;
    int bcol = blockIdx.x * 128;

    float c[2][8][4];
#pragma unroll
    for (int mi = 0; mi < 2; mi++)
#pragma unroll
        for (int nf = 0; nf < 8; nf++)
#pragma unroll
            for (int q = 0; q < 4; q++) c[mi][nf][q] = 0.0f;

    int arow = tid >> 2;
    int akc  = (tid & 3) * 4;
    int bkr  = tid >> 4;
    int bcc  = (tid & 15) * 8;

    for (int k0 = 0; k0 < K; k0 += 16) {
#pragma unroll
        for (int h = 0; h < 2; h++) {
            int r = arow + h * 64;
            float4 v = make_float4(0.f, 0.f, 0.f, 0.f);
            if (brow + r < M)
                v = *(const float4*)(A + (size_t)(brow + r) * K + k0 + akc);
            As[akc + 0][r] = to_tf32(v.x);
            As[akc + 1][r] = to_tf32(v.y);
            As[akc + 2][r] = to_tf32(v.z);
            As[akc + 3][r] = to_tf32(v.w);
        }
#pragma unroll
        for (int h = 0; h < 2; h++) {
            float4 v = *(const float4*)(Bm + (size_t)(k0 + bkr) * N + bcol + bcc + h * 4);
            Bs[bkr][bcc + h * 4 + 0] = to_tf32(v.x);
            Bs[bkr][bcc + h * 4 + 1] = to_tf32(v.y);
            Bs[bkr][bcc + h * 4 + 2] = to_tf32(v.z);
            Bs[bkr][bcc + h * 4 + 3] = to_tf32(v.w);
        }
        __syncthreads();
#pragma unroll
        for (int kk = 0; kk < 16; kk += 8) {
            unsigned a[2][4], b[8][2];
#pragma unroll
            for (int mi = 0; mi < 2; mi++) {
                int row = wm + mi * 16 + g;
                a[mi][0] = As[kk + t][row];
                a[mi][1] = As[kk + t][row + 8];
                a[mi][2] = As[kk + t + 4][row];
                a[mi][3] = As[kk + t + 4][row + 8];
            }
#pragma unroll
            for (int nf = 0; nf < 8; nf++) {
                int col = wn + nf * 8 + g;
                b[nf][0] = Bs[kk + t][col];
                b[nf][1] = Bs[kk + t + 4][col];
            }
#pragma unroll
            for (int mi = 0; mi < 2; mi++)
#pragma unroll
                for (int nf = 0; nf < 8; nf++) {
                    asm volatile(
                        "mma.sync.aligned.m16n8k8.row.col.f32.tf32.tf32.f32 "
                        "{%0,%1,%2,%3}, {%4,%5,%6,%7}, {%8,%9}, {%0,%1,%2,%3};"
                        : "+f"(c[mi][nf][0]), "+f"(c[mi][nf][1]),
                          "+f"(c[mi][nf][2]), "+f"(c[mi][nf][3])
                        : "r"(a[mi][0]), "r"(a[mi][1]), "r"(a[mi][2]), "r"(a[mi][3]),
                          "r"(b[nf][0]), "r"(b[nf][1]));
                }
        }
        __syncthreads();
    }

#pragma unroll
    for (int mi = 0; mi < 2; mi++) {
        int row0 = brow + wm + mi * 16 + g;
#pragma unroll
        for (int nf = 0; nf < 8; nf++) {
            int col = bcol + wn + nf * 8 + 2 * t;
            float v0 = c[mi][nf][0], v1 = c[mi][nf][1];
            float v2 = c[mi][nf][2], v3 = c[mi][nf][3];
            if (RELU) {
                v0 = fmaxf(v0, 0.f); v1 = fmaxf(v1, 0.f);
                v2 = fmaxf(v2, 0.f); v3 = fmaxf(v3, 0.f);
            }
            if (row0 < M)
                *(float2*)(C + (size_t)row0 * N + col) = make_float2(v0, v1);
            if (row0 + 8 < M)
                *(float2*)(C + (size_t)(row0 + 8) * N + col) = make_float2(v2, v3);
        }
    }
}

// ---------------- pack Wl|Wr -> g_Wlr [K][2*dout], float4 ----------------
__global__ void k_packW(const float* __restrict__ Wl, const float* __restrict__ Wr,
                        int K, int dout) {
    int idx = blockIdx.x * blockDim.x + threadIdx.x;
    int tot = K * 2 * dout / 4;
    if (idx >= tot) return;
    int k = idx / (2 * dout / 4), c4 = idx % (2 * dout / 4);
    int c = c4 * 4;
    float4 v = (c < dout) ? *(const float4*)(Wl + (size_t)k * dout + c)
                          : *(const float4*)(Wr + (size_t)k * dout + c - dout);
    *(float4*)(g_Wlr + (size_t)k * 2 * dout + c) = v;
}

// ---------------- fused GAT layer: alpha + online softmax + aggregation (warp/node) ------
template <int NC>   // NC = dout/32
__global__ __launch_bounds__(256) void k_gat(
        const int* __restrict__ src, const float* __restrict__ ea,
        const float* __restrict__ We, const float* __restrict__ att,
        const float* __restrict__ bias, float* __restrict__ hn, int dorelu) {
    const int dout = NC * 32;
    __shared__ float sWe[ED][NC * 32];
    __shared__ float sAtt[NC * 32];
    __shared__ float sB[NC * 32];
    int tid = threadIdx.x;
    for (int i = tid; i < ED * dout; i += 256) sWe[i / dout][i % dout] = We[i];
    for (int i = tid; i < dout; i += 256) { sAtt[i] = att[i]; sB[i] = bias[i]; }
    __syncthreads();

    int lane = tid & 31, w = tid >> 5;
    int n = blockIdx.x * 8 + w;
    if (n >= NN) return;

    const float* xrp = g_xlr + (size_t)n * 2 * dout + dout;
    float xrv[NC];
#pragma unroll
    for (int q = 0; q < NC; q++) xrv[q] = xrp[q * 32 + lane];

    float m = -1e30f, ssum = 0.0f;
    float acc[NC];
#pragma unroll
    for (int q = 0; q < NC; q++) acc[q] = 0.0f;

    int beg = g_off[n], end = g_off[n + 1];
    for (int i = beg; i < end; i++) {
        int e = g_eid[i];
        int s;
        const float* eap;
        if (e < EE) { s = src[e]; eap = ea + (size_t)e * ED; }
        else        { s = e - EE; eap = g_mean + (size_t)s * ED; }
        float eareg = (lane < ED) ? eap[lane] : 0.0f;
        const float* xlp = g_xlr + (size_t)s * 2 * dout;
        float xv[NC];
#pragma unroll
        for (int q = 0; q < NC; q++) xv[q] = xlp[q * 32 + lane];
        float ed[NC];
#pragma unroll
        for (int q = 0; q < NC; q++) ed[q] = 0.0f;
#pragma unroll
        for (int j = 0; j < ED; j++) {
            float aj = __shfl_sync(0xffffffffu, eareg, j);
#pragma unroll
            for (int q = 0; q < NC; q++) ed[q] += aj * sWe[j][q * 32 + lane];
        }
        float p = 0.0f;
#pragma unroll
        for (int q = 0; q < NC; q++) {
            float v = xv[q] + xrv[q] + ed[q];
            v = v > 0.0f ? v : 0.2f * v;
            p += sAtt[q * 32 + lane] * v;
        }
#pragma unroll
        for (int o = 16; o; o >>= 1) p += __shfl_xor_sync(0xffffffffu, p, o);
        // online softmax update
        float nm = fmaxf(m, p);
        float cs = expf(m - nm);
        float ex = expf(p - nm);
        ssum = ssum * cs + ex;
#pragma unroll
        for (int q = 0; q < NC; q++) acc[q] = acc[q] * cs + ex * xv[q];
        m = nm;
    }
    float inv = 1.0f / fmaxf(ssum, 1e-16f);
    float* hp = hn + (size_t)n * dout;
#pragma unroll
    for (int q = 0; q < NC; q++) {
        float v = acc[q] * inv + sB[q * 32 + lane];
        hp[q * 32 + lane] = dorelu ? fmaxf(v, 0.0f) : v;
    }
}

// ---------------- pack Wbi[k,i,j] -> g_UV[i][U(c) | V(c)], float4 ----------------
__global__ void k_pack(const float* __restrict__ Wbi) {
    int idx = blockIdx.x * blockDim.x + threadIdx.x;
    const int tot = HMAX * CB2 / 4;
    if (idx >= tot) return;
    int i = idx / (CB2 / 4), c4 = idx % (CB2 / 4);
    int c = c4 * 4;
    int isV = (c >= CBI);
    int cc = c - isV * CBI;
    int k = cc >> 4, j = cc & 15;
    float4 v = *(const float4*)(Wbi + ((size_t)k * 1024 + isV * 512 + i) * 16 + j);
    *(float4*)(g_UV + (size_t)i * CB2 + c) = v;
}

// ---------------- pad Wm1 into [KP][NP] with bias row ----------------
__global__ void k_packM1(const float* __restrict__ Wm1, const float* __restrict__ bm1) {
    int idx = blockIdx.x * blockDim.x + threadIdx.x;
    if (idx >= KP * NP) return;
    int r = idx / NP, c = idx % NP;
    float v = 0.0f;
    if (c < KBI) {
        if (r < KBI) v = Wm1[(size_t)r * KBI + c];
        else if (r == KBI) v = bm1[c];
    }
    g_Wm1p[idx] = v;
}

// ---------------- bilinear: bi[e][k] = sum_j (A[src]+B[dst])[k*16+j]*ea[j] + bbi[k] -------
__global__ void k_bilin(const int* __restrict__ src, const int* __restrict__ dst,
                        const float* __restrict__ ea, const float* __restrict__ bbi) {
    int tid = threadIdx.x, w = tid >> 5, lane = tid & 31;
    int e = blockIdx.x * 8 + w;
    if (e >= EE) return;
    int s = src[e], d = dst[e];
    int j4 = lane & 3, kk = lane >> 2;
    float4 eav = *(const float4*)(ea + (size_t)e * ED + j4 * 4);
    const __nv_bfloat16* Ap = g_ABb + (size_t)s * CB2;
    const __nv_bfloat16* Bp = g_ABb + (size_t)d * CB2 + CBI;
    float* bo = g_bi + (size_t)e * KP;
#pragma unroll 4
    for (int it = 0; it < 34; it++) {
        int base = (it * 8 + kk) * 16 + j4 * 4;
        float2 a01 = __bfloat1622float2(*(const __nv_bfloat162*)(Ap + base));
        float2 a23 = __bfloat1622float2(*(const __nv_bfloat162*)(Ap + base + 2));
        float2 b01 = __bfloat1622float2(*(const __nv_bfloat162*)(Bp + base));
        float2 b23 = __bfloat1622float2(*(const __nv_bfloat162*)(Bp + base + 2));
        float v = (a01.x + b01.x) * eav.x + (a01.y + b01.y) * eav.y
                + (a23.x + b23.x) * eav.z + (a23.y + b23.y) * eav.w;
        v += __shfl_xor_sync(0xffffffffu, v, 1);
        v += __shfl_xor_sync(0xffffffffu, v, 2);
        if (j4 == 0) {
            int k = it * 8 + kk;
            bo[k] = v + bbi[k];
        }
    }
    if (lane < KP - KBI) bo[KBI + lane] = (lane == 0) ? 1.0f : 0.0f;
}

// ---------------- tail: m2 = relu(m1@Wm2+bm2); out = sigmoid(m2@Wm3+bm3) ------------------
__global__ void k_tail(const float* __restrict__ Wm2, const float* __restrict__ bm2,
                       const float* __restrict__ Wm3, const float* __restrict__ bm3,
                       float* __restrict__ out) {
    int tid = threadIdx.x, w = tid >> 5, lane = tid & 31;
    int e = blockIdx.x * 8 + w;
    if (e >= EE) return;
    const float* m1p = g_m1 + (size_t)e * NP;
    float acc = bm2[lane];
    for (int k0 = 0; k0 < KBI; k0 += 32) {
        float mv = m1p[k0 + lane];
        int jmax = (KBI - k0 < 32) ? (KBI - k0) : 32;
        for (int j = 0; j < jmax; j++) {
            float m = __shfl_sync(0xffffffffu, mv, j);
            acc += m * Wm2[(size_t)(k0 + j) * 32 + lane];
        }
    }
    float m2v = fmaxf(acc, 0.0f);
    float p = m2v * Wm3[lane];
#pragma unroll
    for (int o = 16; o; o >>= 1) p += __shfl_xor_sync(0xffffffffu, p, o);
    if (lane == 0) out[e] = 1.0f / (1.0f + expf(-(p + bm3[0])));
}

// ---------------- host ----------------
static inline dim3 gemm_grid(int M, int Nn) { return dim3(Nn / 128, (M + 127) / 128); }

extern "C" void kernel_launch(void* const* d_in, const int* in_sizes, int n_in,
                              void* d_out, int out_size) {
    const float* x         = (const float*)d_in[0];
    const float* edge_attr = (const float*)d_in[1];
    const int*   eidx      = (const int*)d_in[2];
    const int* src = eidx;
    const int* dst = eidx + EE;
    const float *Wl[4], *Wr[4], *We[4], *att[4], *bb[4];
    for (int l = 0; l < 4; l++) {
        int base = 3 + l * 5;
        Wl[l]  = (const float*)d_in[base + 0];
        Wr[l]  = (const float*)d_in[base + 1];
        We[l]  = (const float*)d_in[base + 2];
        att[l] = (const float*)d_in[base + 3];
        bb[l]  = (const float*)d_in[base + 4];
    }
    const float* Wbi = (const float*)d_in[23];
    const float* bbi = (const float*)d_in[24];
    const float* Wm1 = (const float*)d_in[25];
    const float* bm1 = (const float*)d_in[26];
    const float* Wm2 = (const float*)d_in[27];
    const float* bm2 = (const float*)d_in[28];
    const float* Wm3 = (const float*)d_in[29];
    const float* bm3 = (const float*)d_in[30];
    float* out = (float*)d_out;

    // scratch pointers
    float *h1, *h2, *xlr, *Wlr, *UV, *cnt, *msum, *bi, *m1, *Wm1p;
    __nv_bfloat16* ABb;
    int *deg, *pos;
    cudaGetSymbolAddress((void**)&h1, g_h1);
    cudaGetSymbolAddress((void**)&h2, g_h2);
    cudaGetSymbolAddress((void**)&xlr, g_xlr);
    cudaGetSymbolAddress((void**)&Wlr, g_Wlr);
    cudaGetSymbolAddress((void**)&UV, g_UV);
    cudaGetSymbolAddress((void**)&ABb, g_ABb);
    cudaGetSymbolAddress((void**)&cnt, g_cnt);
    cudaGetSymbolAddress((void**)&msum, g_msum);
    cudaGetSymbolAddress((void**)&deg, g_deg);
    cudaGetSymbolAddress((void**)&pos, g_pos);
    cudaGetSymbolAddress((void**)&bi, g_bi);
    cudaGetSymbolAddress((void**)&m1, g_m1);
    cudaGetSymbolAddress((void**)&Wm1p, g_Wm1p);

    // edge_attr mean for self loops
    cudaMemsetAsync(cnt, 0, NN * sizeof(float));
    cudaMemsetAsync(msum, 0, NN * ED * sizeof(float));
    k_count<<<(EE * ED + 255) / 256, 256>>>(dst, edge_attr);
    k_mean<<<(NN * ED + 255) / 256, 256>>>();

    // CSR build (augmented graph, keyed by dst)
    cudaMemsetAsync(deg, 0, NN * sizeof(int));
    cudaMemsetAsync(pos, 0, NN * sizeof(int));
    k_deg<<<(EA + 255) / 256, 256>>>(dst);
    k_scan<<<1, 1024>>>();
    k_fill<<<(EA + 255) / 256, 256>>>(dst);

    const float* hcur = x;
    int din = 32;
    float* hbufs[2] = { h1, h2 };

    for (int l = 0; l < 4; l++) {
        int dout = (l == 0) ? 256 : 512;
        k_packW<<<(din * 2 * dout / 4 + 255) / 256, 256>>>(Wl[l], Wr[l], din, dout);
        bf16gemm<float><<<gemm_grid(NN, 2 * dout), 256>>>(hcur, Wlr, xlr, NN, 2 * dout, din);
        float* hn = hbufs[l & 1];
        int dorelu = (l < 3) ? 1 : 0;
        if (dout == 256)
            k_gat<8><<<(NN + 7) / 8, 256>>>(src, edge_attr, We[l], att[l], bb[l], hn, dorelu);
        else
            k_gat<16><<<(NN + 7) / 8, 256>>>(src, edge_attr, We[l], att[l], bb[l], hn, dorelu);
        hcur = hn;
        din = dout;
    }

    // edge scoring
    k_pack<<<(HMAX * CB2 / 4 + 255) / 256, 256>>>(Wbi);
    bf16gemm<__nv_bfloat16><<<gemm_grid(NN, CB2), 256>>>(hcur, UV, ABb, NN, CB2, HMAX);
    k_packM1<<<(KP * NP + 255) / 256, 256>>>(Wm1, bm1);
    k_bilin<<<(EE + 7) / 8, 256>>>(src, dst, edge_attr, bbi);
    tf32gemm<true><<<gemm_grid(EE, NP), 256>>>(bi, Wm1p, m1, EE, NP, KP);
    k_tail<<<(EE + 7) / 8, 256>>>(Wm2, bm2, Wm3, bm3, out);
}